// round 9
// baseline (speedup 1.0000x reference)
#include <cuda_runtime.h>
#include <math.h>

#define NN 50000
#define EE 400000
#define HH 8
#define CCH 16
#define DH 128
#define DE 32
#define LL 4

// ---------------- scratch (device globals; no runtime allocation) ----------
__device__ float g_Q[NN * DH];
__device__ float g_K[NN * DH];
__device__ float g_V[NN * DH];
__device__ float g_h0[NN * DH];
__device__ float g_h1[NN * DH];
__device__ float g_Z[NN * 256];   // per-node, per-head q·We   [N][H][32]
__device__ int   g_off[NN + 1];
__device__ int   g_deg[NN + 2];   // tail: [NN]=sync arrivals, [NN+1]=scan-done
__device__ int   g_cur[NN];
__device__ int   g_eid[EE];

// ---------------- f32x2 packed FMA helpers (Blackwell) ---------------------
typedef unsigned long long u64;
__device__ __forceinline__ u64 pack2(float lo, float hi) {
    u64 r; asm("mov.b64 %0,{%1,%2};" : "=l"(r) : "f"(lo), "f"(hi)); return r;
}
__device__ __forceinline__ void fma2(u64 &d, u64 a, u64 b) {
    asm("fma.rn.f32x2 %0,%1,%2,%0;" : "+l"(d) : "l"(a), "l"(b));
}
__device__ __forceinline__ float2 unpack2(u64 v) {
    float2 f; asm("mov.b64 {%0,%1},%2;" : "=f"(f.x), "=f"(f.y) : "l"(v)); return f;
}

// ---------------- CSR build: persistent hist -> scan -> scatter -------------
#define CSR_BLOCKS 256
__global__ void __launch_bounds__(1024, 2) k_csr(const int* __restrict__ dst) {
    const int tid = threadIdx.x;
    const int gt = blockIdx.x * 1024 + tid;
    const int gsz = gridDim.x * 1024;

    for (int e = gt; e < EE; e += gsz) atomicAdd(&g_deg[dst[e]], 1);
    __threadfence();
    __syncthreads();
    if (tid == 0) atomicAdd(&g_deg[NN], 1);

    if (blockIdx.x == 0) {
        if (tid == 0) {
            while (atomicAdd(&g_deg[NN], 0) < (int)gridDim.x) __nanosleep(64);
        }
        __syncthreads();
        __threadfence();
        __shared__ int part[1024];
        const int PER = (NN + 1023) / 1024;
        const int base = tid * PER;
        int sum = 0;
        for (int i = 0; i < PER; i++) { int idx = base + i; if (idx < NN) sum += g_deg[idx]; }
        part[tid] = sum;
        __syncthreads();
        for (int ofs = 1; ofs < 1024; ofs <<= 1) {
            int v = (tid >= ofs) ? part[tid - ofs] : 0;
            __syncthreads();
            part[tid] += v;
            __syncthreads();
        }
        int run = (tid == 0) ? 0 : part[tid - 1];
        for (int i = 0; i < PER; i++) {
            int idx = base + i;
            if (idx <= NN) g_off[idx] = run;
            if (idx < NN) { g_cur[idx] = run; run += g_deg[idx]; }
        }
        __syncthreads();
        __threadfence();
        if (tid == 0) atomicExch(&g_deg[NN + 1], 1);
    } else {
        if (tid == 0) {
            while (atomicAdd(&g_deg[NN + 1], 0) == 0) __nanosleep(128);
        }
        __syncthreads();
        __threadfence();
    }

    for (int e = gt; e < EE; e += gsz) {
        int pos = atomicAdd(&g_cur[dst[e]], 1);
        g_eid[pos] = e;
    }
}

// ---------------- node GEMM: Y = X @ W^T + b, 128x128 tiles, 8x8/thread ----
__global__ void __launch_bounds__(256, 2) gemm128_kernel(
    const float* __restrict__ X,
    const float* __restrict__ W0, const float* __restrict__ W1,
    const float* __restrict__ W2, const float* __restrict__ W3,
    const float* __restrict__ b0, const float* __restrict__ b1,
    const float* __restrict__ b2, const float* __restrict__ b3,
    float* __restrict__ O0, float* __restrict__ O1,
    float* __restrict__ O2, float* __restrict__ O3)
{
    __shared__ __align__(16) float Xs[32][132];
    __shared__ __align__(16) float Ws[32][132];
    const int tid = threadIdx.x;              // 256 threads
    const int tx = tid & 15, ty = tid >> 4;   // 16 x 16
    const int bm0 = blockIdx.x * 128;
    const int mat = blockIdx.y;
    const float* W    = (mat == 0) ? W0 : (mat == 1) ? W1 : (mat == 2) ? W2 : W3;
    const float* bias = (mat == 0) ? b0 : (mat == 1) ? b1 : (mat == 2) ? b2 : b3;
    float*       O    = (mat == 0) ? O0 : (mat == 1) ? O1 : (mat == 2) ? O2 : O3;

    u64 c2[4][8];
#pragma unroll
    for (int p = 0; p < 4; p++)
#pragma unroll
        for (int n = 0; n < 8; n++) c2[p][n] = 0ULL;

    for (int kk = 0; kk < DH; kk += 32) {
#pragma unroll
        for (int i = 0; i < 4; i++) {
            int f = tid + i * 256;            // 0..1023
            int row = f >> 3, c4 = f & 7;
            int node = bm0 + row;
            float4 v = make_float4(0.f, 0.f, 0.f, 0.f);
            if (node < NN)
                v = *reinterpret_cast<const float4*>(X + (size_t)node * DH + kk + c4 * 4);
            Xs[c4 * 4 + 0][row] = v.x; Xs[c4 * 4 + 1][row] = v.y;
            Xs[c4 * 4 + 2][row] = v.z; Xs[c4 * 4 + 3][row] = v.w;
            float4 w = *reinterpret_cast<const float4*>(W + (size_t)row * DH + kk + c4 * 4);
            Ws[c4 * 4 + 0][row] = w.x; Ws[c4 * 4 + 1][row] = w.y;
            Ws[c4 * 4 + 2][row] = w.z; Ws[c4 * 4 + 3][row] = w.w;
        }
        __syncthreads();
#pragma unroll
        for (int k = 0; k < 32; k++) {
            ulonglong2 aA = *reinterpret_cast<const ulonglong2*>(&Xs[k][ty * 4]);
            ulonglong2 aB = *reinterpret_cast<const ulonglong2*>(&Xs[k][64 + ty * 4]);
            u64 ap[4] = {aA.x, aA.y, aB.x, aB.y};
            float4 w0 = *reinterpret_cast<const float4*>(&Ws[k][tx * 4]);
            float4 w1 = *reinterpret_cast<const float4*>(&Ws[k][64 + tx * 4]);
            u64 bb[8] = {pack2(w0.x, w0.x), pack2(w0.y, w0.y),
                         pack2(w0.z, w0.z), pack2(w0.w, w0.w),
                         pack2(w1.x, w1.x), pack2(w1.y, w1.y),
                         pack2(w1.z, w1.z), pack2(w1.w, w1.w)};
#pragma unroll
            for (int p = 0; p < 4; p++)
#pragma unroll
                for (int n = 0; n < 8; n++)
                    fma2(c2[p][n], ap[p], bb[n]);
        }
        __syncthreads();
    }

    const int oc0 = tx * 4, oc1 = 64 + tx * 4;
    float4 ba0 = *reinterpret_cast<const float4*>(bias + oc0);
    float4 ba1 = *reinterpret_cast<const float4*>(bias + oc1);
#pragma unroll
    for (int p = 0; p < 4; p++) {
        int rbase = (p < 2) ? (ty * 4 + 2 * p) : (64 + ty * 4 + 2 * (p - 2));
        float r0[8], r1[8];
#pragma unroll
        for (int n = 0; n < 8; n++) {
            float2 u = unpack2(c2[p][n]);
            r0[n] = u.x; r1[n] = u.y;
        }
        int node0 = bm0 + rbase;
        if (node0 < NN) {
            *reinterpret_cast<float4*>(O + (size_t)node0 * DH + oc0) =
                make_float4(r0[0] + ba0.x, r0[1] + ba0.y, r0[2] + ba0.z, r0[3] + ba0.w);
            *reinterpret_cast<float4*>(O + (size_t)node0 * DH + oc1) =
                make_float4(r0[4] + ba1.x, r0[5] + ba1.y, r0[6] + ba1.z, r0[7] + ba1.w);
        }
        if (node0 + 1 < NN) {
            *reinterpret_cast<float4*>(O + (size_t)(node0 + 1) * DH + oc0) =
                make_float4(r1[0] + ba0.x, r1[1] + ba0.y, r1[2] + ba0.z, r1[3] + ba0.w);
            *reinterpret_cast<float4*>(O + (size_t)(node0 + 1) * DH + oc1) =
                make_float4(r1[4] + ba1.x, r1[5] + ba1.y, r1[6] + ba1.z, r1[7] + ba1.w);
        }
    }
}

// ---------------- Z = per-head Q @ We : Z[n][h*32+d] ------------------------
__global__ void __launch_bounds__(256) z2_kernel(
    const float* __restrict__ Q, const float* __restrict__ We, float* __restrict__ Z)
{
    __shared__ float sQh[128][17];
    __shared__ float sWe[16][36];
    const int tid = threadIdx.x;
    const int h = blockIdx.y;
    const int n0 = blockIdx.x * 128;

#pragma unroll
    for (int i = 0; i < 2; i++) {
        int f = tid + i * 256;                // 0..511
        int node = f >> 2, q4 = f & 3;
        float4 v = make_float4(0.f, 0.f, 0.f, 0.f);
        if (n0 + node < NN)
            v = *reinterpret_cast<const float4*>(Q + (size_t)(n0 + node) * DH + h * 16 + q4 * 4);
        sQh[node][q4 * 4 + 0] = v.x; sQh[node][q4 * 4 + 1] = v.y;
        sQh[node][q4 * 4 + 2] = v.z; sQh[node][q4 * 4 + 3] = v.w;
    }
#pragma unroll
    for (int i = 0; i < 2; i++) {
        int f = tid + i * 256;                // 0..511
        int c = f >> 5, d = f & 31;
        sWe[c][d] = We[(size_t)(h * 16 + c) * DE + d];
    }
    __syncthreads();

    const int n = tid & 127, d0 = (tid >> 7) * 16;
    float z[16];
#pragma unroll
    for (int i = 0; i < 16; i++) z[i] = 0.f;
    for (int c = 0; c < 16; c++) {
        float q = sQh[n][c];
#pragma unroll
        for (int i = 0; i < 4; i++) {
            float4 w = *reinterpret_cast<const float4*>(&sWe[c][d0 + 4 * i]);
            z[4 * i + 0] += q * w.x; z[4 * i + 1] += q * w.y;
            z[4 * i + 2] += q * w.z; z[4 * i + 3] += q * w.w;
        }
    }
    if (n0 + n < NN) {
        float* zp = Z + (size_t)(n0 + n) * 256 + h * 32 + d0;
#pragma unroll
        for (int i = 0; i < 4; i++)
            *reinterpret_cast<float4*>(zp + 4 * i) =
                make_float4(z[4 * i], z[4 * i + 1], z[4 * i + 2], z[4 * i + 3]);
    }
}

// ---------------- per-destination attention (pairwise online softmax) ------
// one warp per destination node; lane l: head h=l>>2, sub j=l&3.
// Two edges per iteration: independent dots, ONE merged accumulator update
// -> halves the serial exp/rescale chain per edge.
__global__ void __launch_bounds__(256, 3) edge_attn_kernel(
    const float* __restrict__ Q, const float* __restrict__ K, const float* __restrict__ V,
    const float* __restrict__ EF, const float* __restrict__ Z,
    const float* __restrict__ We,
    const int* __restrict__ srcArr,
    float* __restrict__ alpha, float* __restrict__ out, int applyGelu)
{
    __shared__ __align__(16) float sWeT[DE][DH + 4];   // [32][132] ~16.9 KB
    const int tid = threadIdx.x;
    for (int i = tid; i < DH * DE; i += blockDim.x) {
        int r = i >> 5, d = i & 31;
        sWeT[d][r] = We[i];
    }
    __syncthreads();

    const int lane = tid & 31;
    const int node = blockIdx.x * 8 + (tid >> 5);
    if (node >= NN) return;
    const int h = lane >> 2, j = lane & 3;
    const unsigned FULL = 0xffffffffu;

    float4 qv = *reinterpret_cast<const float4*>(Q + (size_t)node * DH + lane * 4);

    // z for this lane: Z[node][h*32 + 8j .. +8]
    const float* zp = Z + (size_t)node * 256 + h * 32 + j * 8;
    float4 za = *reinterpret_cast<const float4*>(zp);
    float4 zb = *reinterpret_cast<const float4*>(zp + 4);

    const int pbeg = g_off[node], pend = g_off[node + 1];

    float m = -1e30f, s_h = 0.f;
    float4 accv = make_float4(0.f, 0.f, 0.f, 0.f);
    float g[8];
#pragma unroll
    for (int d = 0; d < 8; d++) g[d] = 0.f;

    for (int p = pbeg; p < pend; p += 2) {
        const bool has1 = (p + 1 < pend);
        int e0 = g_eid[p];
        int e1 = has1 ? g_eid[p + 1] : e0;
        int s0 = srcArr[e0];
        int s1 = has1 ? srcArr[e1] : s0;

        float4 kv0 = *reinterpret_cast<const float4*>(K + (size_t)s0 * DH + lane * 4);
        float4 kv1 = *reinterpret_cast<const float4*>(K + (size_t)s1 * DH + lane * 4);
        float4 vv0 = *reinterpret_cast<const float4*>(V + (size_t)s0 * DH + lane * 4);
        float4 vv1 = *reinterpret_cast<const float4*>(V + (size_t)s1 * DH + lane * 4);
        const float* ef0p = EF + (size_t)e0 * DE + j * 8;
        const float* ef1p = EF + (size_t)e1 * DE + j * 8;
        float4 e0a = __ldg(reinterpret_cast<const float4*>(ef0p));
        float4 e0b = __ldg(reinterpret_cast<const float4*>(ef0p + 4));
        float4 e1a = __ldg(reinterpret_cast<const float4*>(ef1p));
        float4 e1b = __ldg(reinterpret_cast<const float4*>(ef1p + 4));

        float part0 = qv.x * kv0.x + qv.y * kv0.y + qv.z * kv0.z + qv.w * kv0.w
                    + za.x * e0a.x + za.y * e0a.y + za.z * e0a.z + za.w * e0a.w
                    + zb.x * e0b.x + zb.y * e0b.y + zb.z * e0b.z + zb.w * e0b.w;
        float part1 = qv.x * kv1.x + qv.y * kv1.y + qv.z * kv1.z + qv.w * kv1.w
                    + za.x * e1a.x + za.y * e1a.y + za.z * e1a.z + za.w * e1a.w
                    + zb.x * e1b.x + zb.y * e1b.y + zb.z * e1b.z + zb.w * e1b.w;
        part0 += __shfl_xor_sync(FULL, part0, 1, 4);
        part1 += __shfl_xor_sync(FULL, part1, 1, 4);
        part0 += __shfl_xor_sync(FULL, part0, 2, 4);
        part1 += __shfl_xor_sync(FULL, part1, 2, 4);
        float a0 = part0 * 0.25f;                 // / sqrt(C), C=16
        float a1v = part1 * 0.25f;
        float a1 = has1 ? a1v : -1e30f;
        if (j == 0) {
            alpha[(size_t)e0 * HH + h] = a0;      // raw alpha
            if (has1) alpha[(size_t)e1 * HH + h] = a1v;
        }
        float mn = fmaxf(m, fmaxf(a0, a1));
        float sc = __expf(m - mn);                // first iter: exp(-inf)=0
        float w0 = __expf(a0 - mn);
        float w1 = __expf(a1 - mn);               // !has1 -> exp(-inf)=0
        m = mn;
        s_h = s_h * sc + w0 + w1;
        accv.x = accv.x * sc + w0 * vv0.x + w1 * vv1.x;
        accv.y = accv.y * sc + w0 * vv0.y + w1 * vv1.y;
        accv.z = accv.z * sc + w0 * vv0.z + w1 * vv1.z;
        accv.w = accv.w * sc + w0 * vv0.w + w1 * vv1.w;
        g[0] = g[0] * sc + w0 * e0a.x + w1 * e1a.x;
        g[1] = g[1] * sc + w0 * e0a.y + w1 * e1a.y;
        g[2] = g[2] * sc + w0 * e0a.z + w1 * e1a.z;
        g[3] = g[3] * sc + w0 * e0a.w + w1 * e1a.w;
        g[4] = g[4] * sc + w0 * e0b.x + w1 * e1b.x;
        g[5] = g[5] * sc + w0 * e0b.y + w1 * e1b.y;
        g[6] = g[6] * sc + w0 * e0b.z + w1 * e1b.z;
        g[7] = g[7] * sc + w0 * e0b.w + w1 * e1b.w;
    }

    float inv = (s_h > 0.f) ? (1.0f / s_h) : 0.f;

    // normalize alphas: 4 edges/iter (lane j handles edge p0+j)
    __syncwarp();
    for (int p0 = pbeg; p0 < pend; p0 += 4) {
        int p = p0 + j;
        if (p < pend) {
            int ee = g_eid[p];
            float a = alpha[(size_t)ee * HH + h];
            alpha[(size_t)ee * HH + h] = __expf(a - m) * inv;
        }
    }

    // finalize: out = skip + accv/s + (We @ g)/s  via transposed We
    float4 skp = *reinterpret_cast<const float4*>(out + (size_t)node * DH + lane * 4);
    float res[4] = {skp.x + accv.x * inv, skp.y + accv.y * inv,
                    skp.z + accv.z * inv, skp.w + accv.w * inv};
#pragma unroll
    for (int d = 0; d < 32; d++) {
        float gg = __shfl_sync(FULL, g[d & 7], h * 4 + (d >> 3)) * inv;
        float4 w = *reinterpret_cast<const float4*>(&sWeT[d][lane * 4]);
        res[0] += w.x * gg; res[1] += w.y * gg;
        res[2] += w.z * gg; res[3] += w.w * gg;
    }
    if (applyGelu) {
#pragma unroll
        for (int cc = 0; cc < 4; cc++) {
            float xv = res[cc];
            res[cc] = 0.5f * xv * (1.0f + erff(xv * 0.70710678118654752f));
        }
    }
    *reinterpret_cast<float4*>(out + (size_t)node * DH + lane * 4) =
        make_float4(res[0], res[1], res[2], res[3]);
}

// ---------------- launch ----------------------------------------------------
extern "C" void kernel_launch(void* const* d_in, const int* in_sizes, int n_in,
                              void* d_out, int out_size)
{
    const float* x   = (const float*)d_in[0];
    const float* ef  = (const float*)d_in[1];
    const float* Wq  = (const float*)d_in[2];
    const float* bq  = (const float*)d_in[3];
    const float* Wk  = (const float*)d_in[4];
    const float* bk  = (const float*)d_in[5];
    const float* Wv  = (const float*)d_in[6];
    const float* bv  = (const float*)d_in[7];
    const float* We  = (const float*)d_in[8];
    const float* Wsk = (const float*)d_in[9];
    const float* bsk = (const float*)d_in[10];
    const int*  eidx = (const int*)d_in[11];
    const int*  src  = eidx;
    const int*  dst  = eidx + EE;
    float* out = (float*)d_out;

    float *Qp, *Kp, *Vp, *h0, *h1, *Zp;
    int *degp;
    cudaGetSymbolAddress((void**)&Qp, g_Q);
    cudaGetSymbolAddress((void**)&Kp, g_K);
    cudaGetSymbolAddress((void**)&Vp, g_V);
    cudaGetSymbolAddress((void**)&h0, g_h0);
    cudaGetSymbolAddress((void**)&h1, g_h1);
    cudaGetSymbolAddress((void**)&Zp, g_Z);
    cudaGetSymbolAddress((void**)&degp, g_deg);

    const float* hcur = x;
    float* houts[4] = {h0, h1, h0, out};

    // zero g_deg + sync words (memset node, not a kernel launch)
    cudaMemsetAsync(degp, 0, (NN + 2) * sizeof(int));

    // launch order: csr(1), gemm0(2), z2_0(3), edge0(4) <- ncu-profiled slot
    k_csr<<<CSR_BLOCKS, 1024>>>(dst);

    for (int l = 0; l < LL; l++) {
        gemm128_kernel<<<dim3((NN + 127) / 128, 4), 256>>>(
            hcur,
            Wq + (size_t)l * DH * DH, Wk + (size_t)l * DH * DH,
            Wv + (size_t)l * DH * DH, Wsk + (size_t)l * DH * DH,
            bq + l * DH, bk + l * DH, bv + l * DH, bsk + l * DH,
            Qp, Kp, Vp, houts[l]);
        z2_kernel<<<dim3((NN + 127) / 128, 8), 256>>>(
            Qp, We + (size_t)l * DH * DE, Zp);
        edge_attn_kernel<<<(NN + 7) / 8, 256>>>(
            Qp, Kp, Vp, ef, Zp,
            We + (size_t)l * DH * DE,
            src,
            out + (size_t)NN * DH + (size_t)l * EE * HH,
            houts[l], (l < LL - 1) ? 1 : 0);
        hcur = houts[l];
    }
}

// round 11
// speedup vs baseline: 1.0242x; 1.0242x over previous
#include <cuda_runtime.h>
#include <math.h>
#include <stdint.h>

#define NN 50000
#define EE 400000
#define HH 8
#define CCH 16
#define DH 128
#define DE 32
#define LL 4

// ---------------- scratch (device globals; no runtime allocation) ----------
__device__ float g_Q[NN * DH];
__device__ float g_K[NN * DH];
__device__ float g_V[NN * DH];
__device__ float g_h0[NN * DH];
__device__ float g_h1[NN * DH];
__device__ float g_Z[NN * 256];   // per-node, per-head q·We   [N][H][32]
__device__ int   g_off[NN + 1];
__device__ int   g_deg[NN + 2];   // tail: [NN]=sync arrivals, [NN+1]=scan-done
__device__ int   g_cur[NN];
__device__ int   g_eid[EE];
__device__ int   g_esrc[EE];      // src node id, CSR-sorted (kills eid->src chase)

// ---------------- f32x2 packed FMA helpers (Blackwell) ---------------------
typedef unsigned long long u64;
typedef unsigned int u32;
__device__ __forceinline__ u64 pack2(float lo, float hi) {
    u64 r; asm("mov.b64 %0,{%1,%2};" : "=l"(r) : "f"(lo), "f"(hi)); return r;
}
__device__ __forceinline__ void fma2(u64 &d, u64 a, u64 b) {
    asm("fma.rn.f32x2 %0,%1,%2,%0;" : "+l"(d) : "l"(a), "l"(b));
}
__device__ __forceinline__ float2 unpack2(u64 v) {
    float2 f; asm("mov.b64 {%0,%1},%2;" : "=f"(f.x), "=f"(f.y) : "l"(v)); return f;
}

// ---------------- cp.async helpers -----------------------------------------
__device__ __forceinline__ void cpa16(u32 dst, const void* src, int pred) {
    asm volatile("{\n .reg .pred p;\n setp.ne.b32 p, %2, 0;\n"
                 " @p cp.async.ca.shared.global [%0], [%1], 16;\n}\n"
                 :: "r"(dst), "l"(src), "r"(pred));
}
__device__ __forceinline__ void cpa_commit() {
    asm volatile("cp.async.commit_group;" ::: "memory");
}
__device__ __forceinline__ void cpa_wait1() {
    asm volatile("cp.async.wait_group 1;" ::: "memory");
}

// ---------------- CSR build: persistent hist -> scan -> scatter -------------
#define CSR_BLOCKS 256
__global__ void __launch_bounds__(1024, 2) k_csr(const int* __restrict__ dst,
                                                 const int* __restrict__ src) {
    const int tid = threadIdx.x;
    const int gt = blockIdx.x * 1024 + tid;
    const int gsz = gridDim.x * 1024;

    for (int e = gt; e < EE; e += gsz) atomicAdd(&g_deg[dst[e]], 1);
    __threadfence();
    __syncthreads();
    if (tid == 0) atomicAdd(&g_deg[NN], 1);

    if (blockIdx.x == 0) {
        if (tid == 0) {
            while (atomicAdd(&g_deg[NN], 0) < (int)gridDim.x) __nanosleep(64);
        }
        __syncthreads();
        __threadfence();
        __shared__ int part[1024];
        const int PER = (NN + 1023) / 1024;
        const int base = tid * PER;
        int sum = 0;
        for (int i = 0; i < PER; i++) { int idx = base + i; if (idx < NN) sum += g_deg[idx]; }
        part[tid] = sum;
        __syncthreads();
        for (int ofs = 1; ofs < 1024; ofs <<= 1) {
            int v = (tid >= ofs) ? part[tid - ofs] : 0;
            __syncthreads();
            part[tid] += v;
            __syncthreads();
        }
        int run = (tid == 0) ? 0 : part[tid - 1];
        for (int i = 0; i < PER; i++) {
            int idx = base + i;
            if (idx <= NN) g_off[idx] = run;
            if (idx < NN) { g_cur[idx] = run; run += g_deg[idx]; }
        }
        __syncthreads();
        __threadfence();
        if (tid == 0) atomicExch(&g_deg[NN + 1], 1);
    } else {
        if (tid == 0) {
            while (atomicAdd(&g_deg[NN + 1], 0) == 0) __nanosleep(128);
        }
        __syncthreads();
        __threadfence();
    }

    for (int e = gt; e < EE; e += gsz) {
        int pos = atomicAdd(&g_cur[dst[e]], 1);
        g_eid[pos] = e;
        g_esrc[pos] = src[e];
    }
}

// ---------------- node GEMM: Y = X @ W^T + b, 128x128 tiles, 8x8/thread ----
__global__ void __launch_bounds__(256, 2) gemm128_kernel(
    const float* __restrict__ X,
    const float* __restrict__ W0, const float* __restrict__ W1,
    const float* __restrict__ W2, const float* __restrict__ W3,
    const float* __restrict__ b0, const float* __restrict__ b1,
    const float* __restrict__ b2, const float* __restrict__ b3,
    float* __restrict__ O0, float* __restrict__ O1,
    float* __restrict__ O2, float* __restrict__ O3)
{
    __shared__ __align__(16) float Xs[32][132];
    __shared__ __align__(16) float Ws[32][132];
    const int tid = threadIdx.x;              // 256 threads
    const int tx = tid & 15, ty = tid >> 4;   // 16 x 16
    const int bm0 = blockIdx.x * 128;
    const int mat = blockIdx.y;
    const float* W    = (mat == 0) ? W0 : (mat == 1) ? W1 : (mat == 2) ? W2 : W3;
    const float* bias = (mat == 0) ? b0 : (mat == 1) ? b1 : (mat == 2) ? b2 : b3;
    float*       O    = (mat == 0) ? O0 : (mat == 1) ? O1 : (mat == 2) ? O2 : O3;

    u64 c2[4][8];
#pragma unroll
    for (int p = 0; p < 4; p++)
#pragma unroll
        for (int n = 0; n < 8; n++) c2[p][n] = 0ULL;

    for (int kk = 0; kk < DH; kk += 32) {
#pragma unroll
        for (int i = 0; i < 4; i++) {
            int f = tid + i * 256;            // 0..1023
            int row = f >> 3, c4 = f & 7;
            int node = bm0 + row;
            float4 v = make_float4(0.f, 0.f, 0.f, 0.f);
            if (node < NN)
                v = *reinterpret_cast<const float4*>(X + (size_t)node * DH + kk + c4 * 4);
            Xs[c4 * 4 + 0][row] = v.x; Xs[c4 * 4 + 1][row] = v.y;
            Xs[c4 * 4 + 2][row] = v.z; Xs[c4 * 4 + 3][row] = v.w;
            float4 w = *reinterpret_cast<const float4*>(W + (size_t)row * DH + kk + c4 * 4);
            Ws[c4 * 4 + 0][row] = w.x; Ws[c4 * 4 + 1][row] = w.y;
            Ws[c4 * 4 + 2][row] = w.z; Ws[c4 * 4 + 3][row] = w.w;
        }
        __syncthreads();
#pragma unroll
        for (int k = 0; k < 32; k++) {
            ulonglong2 aA = *reinterpret_cast<const ulonglong2*>(&Xs[k][ty * 4]);
            ulonglong2 aB = *reinterpret_cast<const ulonglong2*>(&Xs[k][64 + ty * 4]);
            u64 ap[4] = {aA.x, aA.y, aB.x, aB.y};
            float4 w0 = *reinterpret_cast<const float4*>(&Ws[k][tx * 4]);
            float4 w1 = *reinterpret_cast<const float4*>(&Ws[k][64 + tx * 4]);
            u64 bb[8] = {pack2(w0.x, w0.x), pack2(w0.y, w0.y),
                         pack2(w0.z, w0.z), pack2(w0.w, w0.w),
                         pack2(w1.x, w1.x), pack2(w1.y, w1.y),
                         pack2(w1.z, w1.z), pack2(w1.w, w1.w)};
#pragma unroll
            for (int p = 0; p < 4; p++)
#pragma unroll
                for (int n = 0; n < 8; n++)
                    fma2(c2[p][n], ap[p], bb[n]);
        }
        __syncthreads();
    }

    const int oc0 = tx * 4, oc1 = 64 + tx * 4;
    float4 ba0 = *reinterpret_cast<const float4*>(bias + oc0);
    float4 ba1 = *reinterpret_cast<const float4*>(bias + oc1);
#pragma unroll
    for (int p = 0; p < 4; p++) {
        int rbase = (p < 2) ? (ty * 4 + 2 * p) : (64 + ty * 4 + 2 * (p - 2));
        float r0[8], r1[8];
#pragma unroll
        for (int n = 0; n < 8; n++) {
            float2 u = unpack2(c2[p][n]);
            r0[n] = u.x; r1[n] = u.y;
        }
        int node0 = bm0 + rbase;
        if (node0 < NN) {
            *reinterpret_cast<float4*>(O + (size_t)node0 * DH + oc0) =
                make_float4(r0[0] + ba0.x, r0[1] + ba0.y, r0[2] + ba0.z, r0[3] + ba0.w);
            *reinterpret_cast<float4*>(O + (size_t)node0 * DH + oc1) =
                make_float4(r0[4] + ba1.x, r0[5] + ba1.y, r0[6] + ba1.z, r0[7] + ba1.w);
        }
        if (node0 + 1 < NN) {
            *reinterpret_cast<float4*>(O + (size_t)(node0 + 1) * DH + oc0) =
                make_float4(r1[0] + ba0.x, r1[1] + ba0.y, r1[2] + ba0.z, r1[3] + ba0.w);
            *reinterpret_cast<float4*>(O + (size_t)(node0 + 1) * DH + oc1) =
                make_float4(r1[4] + ba1.x, r1[5] + ba1.y, r1[6] + ba1.z, r1[7] + ba1.w);
        }
    }
}

// ---------------- Z = per-head Q @ We : Z[n][h*32+d] ------------------------
__global__ void __launch_bounds__(256) z2_kernel(
    const float* __restrict__ Q, const float* __restrict__ We, float* __restrict__ Z)
{
    __shared__ float sQh[128][17];
    __shared__ float sWe[16][36];
    const int tid = threadIdx.x;
    const int h = blockIdx.y;
    const int n0 = blockIdx.x * 128;

#pragma unroll
    for (int i = 0; i < 2; i++) {
        int f = tid + i * 256;                // 0..511
        int node = f >> 2, q4 = f & 3;
        float4 v = make_float4(0.f, 0.f, 0.f, 0.f);
        if (n0 + node < NN)
            v = *reinterpret_cast<const float4*>(Q + (size_t)(n0 + node) * DH + h * 16 + q4 * 4);
        sQh[node][q4 * 4 + 0] = v.x; sQh[node][q4 * 4 + 1] = v.y;
        sQh[node][q4 * 4 + 2] = v.z; sQh[node][q4 * 4 + 3] = v.w;
    }
#pragma unroll
    for (int i = 0; i < 2; i++) {
        int f = tid + i * 256;                // 0..511
        int c = f >> 5, d = f & 31;
        sWe[c][d] = We[(size_t)(h * 16 + c) * DE + d];
    }
    __syncthreads();

    const int n = tid & 127, d0 = (tid >> 7) * 16;
    float z[16];
#pragma unroll
    for (int i = 0; i < 16; i++) z[i] = 0.f;
    for (int c = 0; c < 16; c++) {
        float q = sQh[n][c];
#pragma unroll
        for (int i = 0; i < 4; i++) {
            float4 w = *reinterpret_cast<const float4*>(&sWe[c][d0 + 4 * i]);
            z[4 * i + 0] += q * w.x; z[4 * i + 1] += q * w.y;
            z[4 * i + 2] += q * w.z; z[4 * i + 3] += q * w.w;
        }
    }
    if (n0 + n < NN) {
        float* zp = Z + (size_t)(n0 + n) * 256 + h * 32 + d0;
#pragma unroll
        for (int i = 0; i < 4; i++)
            *reinterpret_cast<float4*>(zp + 4 * i) =
                make_float4(z[4 * i], z[4 * i + 1], z[4 * i + 2], z[4 * i + 3]);
    }
}

// ---------------- per-destination attention (online softmax, cp.async) -----
// one warp per destination node; lane l: head h=l>>2, sub j=l&3.
// K/V/EF rows prefetched via 2-stage cp.async pipeline into per-warp smem.
__global__ void __launch_bounds__(256, 3) edge_attn_kernel(
    const float* __restrict__ Q, const float* __restrict__ K, const float* __restrict__ V,
    const float* __restrict__ EF, const float* __restrict__ Z,
    const float* __restrict__ We,
    float* __restrict__ alpha, float* __restrict__ out, int applyGelu)
{
    __shared__ __align__(16) float sWeT[DE][DH + 4];     // 16.9 KB
    __shared__ __align__(16) float sK [8][2][DH];        // 8 KB
    __shared__ __align__(16) float sV [8][2][DH];        // 8 KB
    __shared__ __align__(16) float sEF[8][2][DE];        // 2 KB
    const int tid = threadIdx.x;
    for (int i = tid; i < DH * DE; i += blockDim.x) {
        int r = i >> 5, d = i & 31;
        sWeT[d][r] = We[i];
    }
    __syncthreads();

    const int lane = tid & 31;
    const int w = tid >> 5;
    const int node = blockIdx.x * 8 + w;
    if (node >= NN) return;
    const int h = lane >> 2, j = lane & 3;
    const unsigned FULL = 0xffffffffu;

    const u32 kA = (u32)__cvta_generic_to_shared(&sK[w][0][0]);
    const u32 vA = (u32)__cvta_generic_to_shared(&sV[w][0][0]);
    const u32 eA = (u32)__cvta_generic_to_shared(&sEF[w][0][0]);

    float4 qv = *reinterpret_cast<const float4*>(Q + (size_t)node * DH + lane * 4);

    // z for this lane: Z[node][h*32 + 8j .. +8]
    const float* zp = Z + (size_t)node * 256 + h * 32 + j * 8;
    float4 za = *reinterpret_cast<const float4*>(zp);
    float4 zb = *reinterpret_cast<const float4*>(zp + 4);

    const int pbeg = g_off[node], pend = g_off[node + 1];

    float m = -1e30f, s_h = 0.f;
    float4 accv = make_float4(0.f, 0.f, 0.f, 0.f);
    float g[8];
#pragma unroll
    for (int d = 0; d < 8; d++) g[d] = 0.f;

    // stage 0 prefetch
    int e_c = 0;
    if (pbeg < pend) {
        e_c = g_eid[pbeg];
        int s0 = g_esrc[pbeg];
        cpa16(kA + lane * 16, K + (size_t)s0 * DH + lane * 4, 1);
        cpa16(vA + lane * 16, V + (size_t)s0 * DH + lane * 4, 1);
        cpa16(eA + lane * 16, EF + (size_t)e_c * DE + lane * 4, lane < 8);
    }
    cpa_commit();

    for (int p = pbeg; p < pend; p++) {
        const int i = p - pbeg;
        const int hasn = (p + 1 < pend) ? 1 : 0;
        int e_n = 0, s_n = 0;
        if (hasn) { e_n = g_eid[p + 1]; s_n = g_esrc[p + 1]; }
        const u32 so = (u32)((i + 1) & 1);
        cpa16(kA + so * 512 + lane * 16, K + (size_t)s_n * DH + lane * 4, hasn);
        cpa16(vA + so * 512 + lane * 16, V + (size_t)s_n * DH + lane * 4, hasn);
        cpa16(eA + so * 128 + lane * 16, EF + (size_t)e_n * DE + lane * 4, hasn && (lane < 8));
        cpa_commit();
        cpa_wait1();
        __syncwarp();

        const int st = i & 1;
        float4 kv  = *reinterpret_cast<const float4*>(&sK[w][st][lane * 4]);
        float4 vv  = *reinterpret_cast<const float4*>(&sV[w][st][lane * 4]);
        float4 efa = *reinterpret_cast<const float4*>(&sEF[w][st][j * 8]);
        float4 efb = *reinterpret_cast<const float4*>(&sEF[w][st][j * 8 + 4]);

        float part = qv.x * kv.x + qv.y * kv.y + qv.z * kv.z + qv.w * kv.w
                   + za.x * efa.x + za.y * efa.y + za.z * efa.z + za.w * efa.w
                   + zb.x * efb.x + zb.y * efb.y + zb.z * efb.z + zb.w * efb.w;
        part += __shfl_xor_sync(FULL, part, 1, 4);
        part += __shfl_xor_sync(FULL, part, 2, 4);
        float a = part * 0.25f;                 // / sqrt(C), C=16
        if (j == 0) alpha[(size_t)e_c * HH + h] = a;   // raw alpha
        float mn = fmaxf(m, a);
        float scale = __expf(m - mn);           // first iter: exp(-inf)=0
        float wgt = __expf(a - mn);
        m = mn;
        s_h = s_h * scale + wgt;
        accv.x = accv.x * scale + wgt * vv.x;
        accv.y = accv.y * scale + wgt * vv.y;
        accv.z = accv.z * scale + wgt * vv.z;
        accv.w = accv.w * scale + wgt * vv.w;
        g[0] = g[0] * scale + wgt * efa.x; g[1] = g[1] * scale + wgt * efa.y;
        g[2] = g[2] * scale + wgt * efa.z; g[3] = g[3] * scale + wgt * efa.w;
        g[4] = g[4] * scale + wgt * efb.x; g[5] = g[5] * scale + wgt * efb.y;
        g[6] = g[6] * scale + wgt * efb.z; g[7] = g[7] * scale + wgt * efb.w;

        e_c = e_n;
    }

    float inv = (s_h > 0.f) ? (1.0f / s_h) : 0.f;

    // normalize alphas: 4 edges/iter (lane j handles edge p0+j)
    __syncwarp();
    for (int p0 = pbeg; p0 < pend; p0 += 4) {
        int p = p0 + j;
        if (p < pend) {
            int ee = g_eid[p];
            float a = alpha[(size_t)ee * HH + h];
            alpha[(size_t)ee * HH + h] = __expf(a - m) * inv;
        }
    }

    // finalize: out = skip + accv/s + (We @ g)/s  via transposed We
    float4 skp = *reinterpret_cast<const float4*>(out + (size_t)node * DH + lane * 4);
    float res[4] = {skp.x + accv.x * inv, skp.y + accv.y * inv,
                    skp.z + accv.z * inv, skp.w + accv.w * inv};
#pragma unroll
    for (int d = 0; d < 32; d++) {
        float gg = __shfl_sync(FULL, g[d & 7], h * 4 + (d >> 3)) * inv;
        float4 wv = *reinterpret_cast<const float4*>(&sWeT[d][lane * 4]);
        res[0] += wv.x * gg; res[1] += wv.y * gg;
        res[2] += wv.z * gg; res[3] += wv.w * gg;
    }
    if (applyGelu) {
#pragma unroll
        for (int cc = 0; cc < 4; cc++) {
            float xv = res[cc];
            res[cc] = 0.5f * xv * (1.0f + erff(xv * 0.70710678118654752f));
        }
    }
    *reinterpret_cast<float4*>(out + (size_t)node * DH + lane * 4) =
        make_float4(res[0], res[1], res[2], res[3]);
}

// ---------------- launch ----------------------------------------------------
extern "C" void kernel_launch(void* const* d_in, const int* in_sizes, int n_in,
                              void* d_out, int out_size)
{
    const float* x   = (const float*)d_in[0];
    const float* ef  = (const float*)d_in[1];
    const float* Wq  = (const float*)d_in[2];
    const float* bq  = (const float*)d_in[3];
    const float* Wk  = (const float*)d_in[4];
    const float* bk  = (const float*)d_in[5];
    const float* Wv  = (const float*)d_in[6];
    const float* bv  = (const float*)d_in[7];
    const float* We  = (const float*)d_in[8];
    const float* Wsk = (const float*)d_in[9];
    const float* bsk = (const float*)d_in[10];
    const int*  eidx = (const int*)d_in[11];
    const int*  src  = eidx;
    const int*  dst  = eidx + EE;
    float* out = (float*)d_out;

    float *Qp, *Kp, *Vp, *h0, *h1, *Zp;
    int *degp;
    cudaGetSymbolAddress((void**)&Qp, g_Q);
    cudaGetSymbolAddress((void**)&Kp, g_K);
    cudaGetSymbolAddress((void**)&Vp, g_V);
    cudaGetSymbolAddress((void**)&h0, g_h0);
    cudaGetSymbolAddress((void**)&h1, g_h1);
    cudaGetSymbolAddress((void**)&Zp, g_Z);
    cudaGetSymbolAddress((void**)&degp, g_deg);

    const float* hcur = x;
    float* houts[4] = {h0, h1, h0, out};

    // zero g_deg + sync words (memset node, not a kernel launch)
    cudaMemsetAsync(degp, 0, (NN + 2) * sizeof(int));

    // launch order: csr(1), gemm0(2), z2_0(3), edge0(4) <- ncu-profiled slot
    k_csr<<<CSR_BLOCKS, 1024>>>(dst, src);

    for (int l = 0; l < LL; l++) {
        gemm128_kernel<<<dim3((NN + 127) / 128, 4), 256>>>(
            hcur,
            Wq + (size_t)l * DH * DH, Wk + (size_t)l * DH * DH,
            Wv + (size_t)l * DH * DH, Wsk + (size_t)l * DH * DH,
            bq + l * DH, bk + l * DH, bv + l * DH, bsk + l * DH,
            Qp, Kp, Vp, houts[l]);
        z2_kernel<<<dim3((NN + 127) / 128, 8), 256>>>(
            Qp, We + (size_t)l * DH * DE, Zp);
        edge_attn_kernel<<<(NN + 7) / 8, 256>>>(
            Qp, Kp, Vp, ef, Zp,
            We + (size_t)l * DH * DE,
            out + (size_t)NN * DH + (size_t)l * EE * HH,
            houts[l], (l < LL - 1) ? 1 : 0);
        hcur = houts[l];
    }
}